// round 2
// baseline (speedup 1.0000x reference)
#include <cuda_runtime.h>

// ---------------- problem constants ----------------
#define TBS   128          // T*B = 4*32
#define SEQ   81           // 9*9
#define CH    128          // width C
#define MROWS (TBS*SEQ)    // 10368 rows
#define NQKV  384          // 3*C

// ---------------- scratch (static device globals; no allocation) ------------
__device__ float g_h  [MROWS*CH];    // residual stream
__device__ float g_n  [MROWS*CH];    // layernorm output
__device__ float g_qkv[MROWS*NQKV];  // qkv projection
__device__ float g_att[MROWS*CH];    // attention output

// ---------------- packed f32x2 helpers (FFMA2 path, sm_100+) ----------------
__device__ __forceinline__ unsigned long long pk2(float x, float y) {
    unsigned long long r;
    asm("mov.b64 %0, {%1, %2};"
        : "=l"(r) : "r"(__float_as_uint(x)), "r"(__float_as_uint(y)));
    return r;
}
__device__ __forceinline__ unsigned long long fma2(unsigned long long a,
                                                   unsigned long long b,
                                                   unsigned long long c) {
    unsigned long long d;
    asm("fma.rn.f32x2 %0, %1, %2, %3;" : "=l"(d) : "l"(a), "l"(b), "l"(c));
    return d;
}
__device__ __forceinline__ void upk2(unsigned long long v, float& x, float& y) {
    unsigned int lo, hi;
    asm("mov.b64 {%0, %1}, %2;" : "=r"(lo), "=r"(hi) : "l"(v));
    x = __uint_as_float(lo);
    y = __uint_as_float(hi);
}
__device__ __forceinline__ float ex2(float x) {
    float r;
    asm("ex2.approx.f32 %0, %1;" : "=f"(r) : "f"(x));   // guaranteed MUFU.EX2
    return r;
}

// ---------------- input projection: h = x @ in_w + in_b ---------------------
__global__ void inproj_kernel(const float* __restrict__ x,
                              const float* __restrict__ in_w,
                              const float* __restrict__ in_b) {
    int m = blockIdx.x;
    int c = threadIdx.x;
    float x0 = __ldg(&x[m * 2]);
    float x1 = __ldg(&x[m * 2 + 1]);
    g_h[(size_t)m * CH + c] = fmaf(x0, in_w[c], fmaf(x1, in_w[CH + c], in_b[c]));
}

// ---------------- layernorm over C, one warp per row -------------------------
__global__ void ln_kernel(const float* __restrict__ gam,
                          const float* __restrict__ bet) {
    int row  = blockIdx.x * 8 + (threadIdx.x >> 5);
    int lane = threadIdx.x & 31;
    const float* hr = g_h + (size_t)row * CH;
    float v0 = hr[lane], v1 = hr[lane + 32], v2 = hr[lane + 64], v3 = hr[lane + 96];
    float s = v0 + v1 + v2 + v3;
#pragma unroll
    for (int o = 16; o; o >>= 1) s += __shfl_xor_sync(0xffffffffu, s, o);
    float mu = s * (1.0f / CH);
    float d0 = v0 - mu, d1 = v1 - mu, d2 = v2 - mu, d3 = v3 - mu;
    float ss = d0 * d0 + d1 * d1 + d2 * d2 + d3 * d3;
#pragma unroll
    for (int o = 16; o; o >>= 1) ss += __shfl_xor_sync(0xffffffffu, ss, o);
    float rstd = rsqrtf(ss * (1.0f / CH) + 1e-5f);
    float* nr = g_n + (size_t)row * CH;
    nr[lane]      = d0 * rstd * gam[lane]      + bet[lane];
    nr[lane + 32] = d1 * rstd * gam[lane + 32] + bet[lane + 32];
    nr[lane + 64] = d2 * rstd * gam[lane + 64] + bet[lane + 64];
    nr[lane + 96] = d3 * rstd * gam[lane + 96] + bet[lane + 96];
}

// ---------------- register-tiled sgemm with packed FFMA2 ---------------------
template <int MODE>
__global__ void __launch_bounds__(256) gemm_kernel(const float* __restrict__ B,
                                                   const float* __restrict__ bias) {
    constexpr int N = (MODE == 0) ? NQKV : CH;
    constexpr int K = CH;
    const float* A = (MODE == 0) ? g_n : g_att;

    __shared__ float As[16][64];   // transposed: As[k][m]
    __shared__ float Bs[16][64];

    int tid = threadIdx.x;
    int tx  = tid & 15;
    int ty  = tid >> 4;

    unsigned long long acc[4][2];
#pragma unroll
    for (int m = 0; m < 4; m++) { acc[m][0] = 0ull; acc[m][1] = 0ull; }

    int ar = tid >> 2;
    int ac = (tid & 3) << 2;
    int br = tid >> 4;
    int bc = (tid & 15) << 2;

    const float* Aload = A + ((size_t)blockIdx.y * 64 + ar) * K + ac;
    const float* Bload = B + (size_t)br * N + blockIdx.x * 64 + bc;

    for (int k0 = 0; k0 < K; k0 += 16) {
        float4 av = *(const float4*)(Aload + k0);
        float4 bv = *(const float4*)(Bload + (size_t)k0 * N);
        As[ac + 0][ar] = av.x;
        As[ac + 1][ar] = av.y;
        As[ac + 2][ar] = av.z;
        As[ac + 3][ar] = av.w;
        *(float4*)&Bs[br][bc] = bv;
        __syncthreads();
#pragma unroll
        for (int k = 0; k < 16; k++) {
            float4 b4 = *(const float4*)&Bs[k][tx << 2];
            unsigned long long b01 = pk2(b4.x, b4.y);
            unsigned long long b23 = pk2(b4.z, b4.w);
#pragma unroll
            for (int m = 0; m < 4; m++) {
                float a = As[k][(ty << 2) + m];
                unsigned long long aa = pk2(a, a);
                acc[m][0] = fma2(aa, b01, acc[m][0]);
                acc[m][1] = fma2(aa, b23, acc[m][1]);
            }
        }
        __syncthreads();
    }

    int col = blockIdx.x * 64 + (tx << 2);
    float bb0 = bias[col], bb1 = bias[col + 1], bb2 = bias[col + 2], bb3 = bias[col + 3];
#pragma unroll
    for (int m = 0; m < 4; m++) {
        int row = blockIdx.y * 64 + (ty << 2) + m;
        float r0, r1, r2, r3;
        upk2(acc[m][0], r0, r1);
        upk2(acc[m][1], r2, r3);
        r0 += bb0; r1 += bb1; r2 += bb2; r3 += bb3;
        if (MODE == 0) {
            *(float4*)(g_qkv + (size_t)row * NQKV + col) = make_float4(r0, r1, r2, r3);
        } else {
            r0 = fmaxf(r0, 0.f); r1 = fmaxf(r1, 0.f);
            r2 = fmaxf(r2, 0.f); r3 = fmaxf(r3, 0.f);
            float4 old = *(const float4*)(g_h + (size_t)row * CH + col);
            *(float4*)(g_h + (size_t)row * CH + col) =
                make_float4(old.x + r0, old.y + r1, old.z + r2, old.w + r3);
        }
    }
}

// ---------------- fused per-channel attention --------------------------------
// q-tile = 9 rows per block -> grid (9, TBS) = 1152 blocks, ~50 regs/thread.
// For each (b, c): att[q] = sum_k exp(q_q*k_k) v_k / sum_k exp(q_q*k_k)
#define QT 9
__global__ void __launch_bounds__(128) attn_kernel() {
    int b  = blockIdx.y;
    int q0 = blockIdx.x * QT;
    int c  = threadIdx.x;

    __shared__ float ks[SEQ][CH];   // all 81 k rows for this batch
    __shared__ float vs[SEQ][CH];

    const float* base = g_qkv + (size_t)b * SEQ * NQKV;
    const float LOG2E = 1.4426950408889634f;

    // cooperative load of full k/v block (81 rows x 128 ch, each thread owns col c)
#pragma unroll 1
    for (int r = 0; r < SEQ; r++) {
        ks[r][c] = base[(size_t)r * NQKV + CH     + c];
        vs[r][c] = base[(size_t)r * NQKV + 2 * CH + c];
    }

    float qv[QT], num[QT], den[QT];
#pragma unroll
    for (int i = 0; i < QT; i++) {
        qv[i]  = base[(size_t)(q0 + i) * NQKV + c] * LOG2E;
        num[i] = 0.f;
        den[i] = 0.f;
    }
    __syncthreads();

#pragma unroll 3
    for (int r = 0; r < SEQ; r++) {
        float kk = ks[r][c];
        float vv = vs[r][c];
#pragma unroll
        for (int i = 0; i < QT; i++) {
            float e = ex2(qv[i] * kk);            // FMUL + MUFU.EX2
            num[i] = fmaf(e, vv, num[i]);
            den[i] += e;
        }
    }

    float* op = g_att + ((size_t)b * SEQ + q0) * CH + c;
#pragma unroll
    for (int i = 0; i < QT; i++) op[(size_t)i * CH] = __fdividef(num[i], den[i]);
}

// ---------------- final projection: out = h @ out_w + out_b ------------------
__global__ void outproj_kernel(const float* __restrict__ ow,
                               const float* __restrict__ ob,
                               float* __restrict__ out) {
    int row  = blockIdx.x * 8 + (threadIdx.x >> 5);
    int lane = threadIdx.x & 31;
    const float* hr = g_h + (size_t)row * CH;
    float a0 = 0.f, a1 = 0.f, a2 = 0.f, a3 = 0.f;
#pragma unroll
    for (int j = 0; j < 4; j++) {
        int cidx = lane + 32 * j;
        float hv = hr[cidx];
        const float* w = ow + cidx * 4;
        a0 = fmaf(hv, w[0], a0);
        a1 = fmaf(hv, w[1], a1);
        a2 = fmaf(hv, w[2], a2);
        a3 = fmaf(hv, w[3], a3);
    }
#pragma unroll
    for (int o = 16; o; o >>= 1) {
        a0 += __shfl_xor_sync(0xffffffffu, a0, o);
        a1 += __shfl_xor_sync(0xffffffffu, a1, o);
        a2 += __shfl_xor_sync(0xffffffffu, a2, o);
        a3 += __shfl_xor_sync(0xffffffffu, a3, o);
    }
    if (lane == 0) {
        *(float4*)(out + (size_t)row * 4) =
            make_float4(a0 + ob[0], a1 + ob[1], a2 + ob[2], a3 + ob[3]);
    }
}

// ---------------- launch -----------------------------------------------------
extern "C" void kernel_launch(void* const* d_in, const int* in_sizes, int n_in,
                              void* d_out, int out_size) {
    const float* x      = (const float*)d_in[0];
    const float* in_w   = (const float*)d_in[1];
    const float* in_b   = (const float*)d_in[2];
    const float* ln_g   = (const float*)d_in[3];
    const float* ln_b   = (const float*)d_in[4];
    const float* qkv_w  = (const float*)d_in[5];
    const float* qkv_b  = (const float*)d_in[6];
    const float* full_w = (const float*)d_in[7];
    const float* full_b = (const float*)d_in[8];
    const float* out_w  = (const float*)d_in[9];
    const float* out_b  = (const float*)d_in[10];
    float* out = (float*)d_out;

    inproj_kernel<<<MROWS, CH>>>(x, in_w, in_b);

    for (int l = 0; l < 4; l++) {
        ln_kernel<<<MROWS / 8, 256>>>(ln_g + l * CH, ln_b + l * CH);
        gemm_kernel<0><<<dim3(NQKV / 64, MROWS / 64), 256>>>(
            qkv_w + (size_t)l * CH * NQKV, qkv_b + l * NQKV);
        attn_kernel<<<dim3(SEQ / QT, TBS), 128>>>();
        gemm_kernel<1><<<dim3(CH / 64, MROWS / 64), 256>>>(
            full_w + (size_t)l * CH * CH, full_b + l * CH);
    }

    outproj_kernel<<<MROWS / 8, 256>>>(out_w, out_b, out);
}

// round 3
// speedup vs baseline: 1.8481x; 1.8481x over previous
#include <cuda_runtime.h>

// ---------------- problem constants ----------------
#define TBS   128          // T*B = 4*32
#define SEQ   81           // 9*9
#define CH    128          // width C
#define MROWS (TBS*SEQ)    // 10368 rows
#define NQKV  384          // 3*C

// ---------------- scratch (static device globals; no allocation) ------------
__device__ float g_h  [MROWS*CH];    // residual stream
__device__ float g_n  [MROWS*CH];    // layernorm output
__device__ float g_qkv[MROWS*NQKV];  // qkv projection
__device__ float g_att[MROWS*CH];    // attention output

// ---------------- packed f32x2 helpers (FFMA2 path, sm_100+) ----------------
__device__ __forceinline__ unsigned long long pk2(float x, float y) {
    unsigned long long r;
    asm("mov.b64 %0, {%1, %2};"
        : "=l"(r) : "r"(__float_as_uint(x)), "r"(__float_as_uint(y)));
    return r;
}
__device__ __forceinline__ unsigned long long fma2(unsigned long long a,
                                                   unsigned long long b,
                                                   unsigned long long c) {
    unsigned long long d;
    asm("fma.rn.f32x2 %0, %1, %2, %3;" : "=l"(d) : "l"(a), "l"(b), "l"(c));
    return d;
}
__device__ __forceinline__ void upk2(unsigned long long v, float& x, float& y) {
    unsigned int lo, hi;
    asm("mov.b64 {%0, %1}, %2;" : "=r"(lo), "=r"(hi) : "l"(v));
    x = __uint_as_float(lo);
    y = __uint_as_float(hi);
}
__device__ __forceinline__ float ex2(float x) {
    float r;
    asm("ex2.approx.f32 %0, %1;" : "=f"(r) : "f"(x));   // guaranteed MUFU.EX2
    return r;
}

// ---------------- input projection: h = x @ in_w + in_b ---------------------
__global__ void inproj_kernel(const float* __restrict__ x,
                              const float* __restrict__ in_w,
                              const float* __restrict__ in_b) {
    int m = blockIdx.x;
    int c = threadIdx.x;
    float x0 = __ldg(&x[m * 2]);
    float x1 = __ldg(&x[m * 2 + 1]);
    g_h[(size_t)m * CH + c] = fmaf(x0, in_w[c], fmaf(x1, in_w[CH + c], in_b[c]));
}

// ---------------- layernorm over C, one warp per row -------------------------
__global__ void ln_kernel(const float* __restrict__ gam,
                          const float* __restrict__ bet) {
    int row  = blockIdx.x * 8 + (threadIdx.x >> 5);
    int lane = threadIdx.x & 31;
    const float* hr = g_h + (size_t)row * CH;
    float v0 = hr[lane], v1 = hr[lane + 32], v2 = hr[lane + 64], v3 = hr[lane + 96];
    float s = v0 + v1 + v2 + v3;
#pragma unroll
    for (int o = 16; o; o >>= 1) s += __shfl_xor_sync(0xffffffffu, s, o);
    float mu = s * (1.0f / CH);
    float d0 = v0 - mu, d1 = v1 - mu, d2 = v2 - mu, d3 = v3 - mu;
    float ss = d0 * d0 + d1 * d1 + d2 * d2 + d3 * d3;
#pragma unroll
    for (int o = 16; o; o >>= 1) ss += __shfl_xor_sync(0xffffffffu, ss, o);
    float rstd = rsqrtf(ss * (1.0f / CH) + 1e-5f);
    float* nr = g_n + (size_t)row * CH;
    nr[lane]      = d0 * rstd * gam[lane]      + bet[lane];
    nr[lane + 32] = d1 * rstd * gam[lane + 32] + bet[lane + 32];
    nr[lane + 64] = d2 * rstd * gam[lane + 64] + bet[lane + 64];
    nr[lane + 96] = d3 * rstd * gam[lane + 96] + bet[lane + 96];
}

// ---------------- register-tiled sgemm with packed FFMA2 ---------------------
template <int MODE>
__global__ void __launch_bounds__(256) gemm_kernel(const float* __restrict__ B,
                                                   const float* __restrict__ bias) {
    constexpr int N = (MODE == 0) ? NQKV : CH;
    constexpr int K = CH;
    const float* A = (MODE == 0) ? g_n : g_att;

    __shared__ float As[16][64];   // transposed: As[k][m]
    __shared__ float Bs[16][64];

    int tid = threadIdx.x;
    int tx  = tid & 15;
    int ty  = tid >> 4;

    unsigned long long acc[4][2];
#pragma unroll
    for (int m = 0; m < 4; m++) { acc[m][0] = 0ull; acc[m][1] = 0ull; }

    int ar = tid >> 2;
    int ac = (tid & 3) << 2;
    int br = tid >> 4;
    int bc = (tid & 15) << 2;

    const float* Aload = A + ((size_t)blockIdx.y * 64 + ar) * K + ac;
    const float* Bload = B + (size_t)br * N + blockIdx.x * 64 + bc;

    for (int k0 = 0; k0 < K; k0 += 16) {
        float4 av = *(const float4*)(Aload + k0);
        float4 bv = *(const float4*)(Bload + (size_t)k0 * N);
        As[ac + 0][ar] = av.x;
        As[ac + 1][ar] = av.y;
        As[ac + 2][ar] = av.z;
        As[ac + 3][ar] = av.w;
        *(float4*)&Bs[br][bc] = bv;
        __syncthreads();
#pragma unroll
        for (int k = 0; k < 16; k++) {
            float4 b4 = *(const float4*)&Bs[k][tx << 2];
            unsigned long long b01 = pk2(b4.x, b4.y);
            unsigned long long b23 = pk2(b4.z, b4.w);
#pragma unroll
            for (int m = 0; m < 4; m++) {
                float a = As[k][(ty << 2) + m];
                unsigned long long aa = pk2(a, a);
                acc[m][0] = fma2(aa, b01, acc[m][0]);
                acc[m][1] = fma2(aa, b23, acc[m][1]);
            }
        }
        __syncthreads();
    }

    int col = blockIdx.x * 64 + (tx << 2);
    float bb0 = bias[col], bb1 = bias[col + 1], bb2 = bias[col + 2], bb3 = bias[col + 3];
#pragma unroll
    for (int m = 0; m < 4; m++) {
        int row = blockIdx.y * 64 + (ty << 2) + m;
        float r0, r1, r2, r3;
        upk2(acc[m][0], r0, r1);
        upk2(acc[m][1], r2, r3);
        r0 += bb0; r1 += bb1; r2 += bb2; r3 += bb3;
        if (MODE == 0) {
            *(float4*)(g_qkv + (size_t)row * NQKV + col) = make_float4(r0, r1, r2, r3);
        } else {
            r0 = fmaxf(r0, 0.f); r1 = fmaxf(r1, 0.f);
            r2 = fmaxf(r2, 0.f); r3 = fmaxf(r3, 0.f);
            float4 old = *(const float4*)(g_h + (size_t)row * CH + col);
            *(float4*)(g_h + (size_t)row * CH + col) =
                make_float4(old.x + r0, old.y + r1, old.z + r2, old.w + r3);
        }
    }
}

// ---------------- fused per-channel attention --------------------------------
// QT=9 q-rows per block, k/v tiled in 27-row chunks (27.6KB smem).
// grid (9, 128) = 1152 blocks, ~45 regs -> 8 CTAs/SM residency, ~31 warps/SM.
#define QT 9
#define KT 27
__global__ void __launch_bounds__(128) attn_kernel() {
    int b  = blockIdx.y;
    int q0 = blockIdx.x * QT;
    int c  = threadIdx.x;

    __shared__ float ks[KT][CH];
    __shared__ float vs[KT][CH];

    const float* base = g_qkv + (size_t)b * SEQ * NQKV;
    const float LOG2E = 1.4426950408889634f;

    float qv[QT], num[QT], den[QT];
#pragma unroll
    for (int i = 0; i < QT; i++) {
        qv[i]  = base[(size_t)(q0 + i) * NQKV + c] * LOG2E;
        num[i] = 0.f;
        den[i] = 0.f;
    }

#pragma unroll 1
    for (int kc = 0; kc < SEQ; kc += KT) {
        __syncthreads();
#pragma unroll
        for (int r = 0; r < KT; r++) {           // fully unrolled: LDGs batch (MLP)
            ks[r][c] = base[(size_t)(kc + r) * NQKV + CH     + c];
            vs[r][c] = base[(size_t)(kc + r) * NQKV + 2 * CH + c];
        }
        __syncthreads();
#pragma unroll 3
        for (int r = 0; r < KT; r++) {
            float kk = ks[r][c];
            float vv = vs[r][c];
#pragma unroll
            for (int i = 0; i < QT; i++) {
                float e = ex2(qv[i] * kk);        // FMUL + MUFU.EX2
                num[i] = fmaf(e, vv, num[i]);
                den[i] += e;
            }
        }
    }

    float* op = g_att + ((size_t)b * SEQ + q0) * CH + c;
#pragma unroll
    for (int i = 0; i < QT; i++) op[(size_t)i * CH] = __fdividef(num[i], den[i]);
}

// ---------------- final projection: out = h @ out_w + out_b ------------------
__global__ void outproj_kernel(const float* __restrict__ ow,
                               const float* __restrict__ ob,
                               float* __restrict__ out) {
    int row  = blockIdx.x * 8 + (threadIdx.x >> 5);
    int lane = threadIdx.x & 31;
    const float* hr = g_h + (size_t)row * CH;
    float a0 = 0.f, a1 = 0.f, a2 = 0.f, a3 = 0.f;
#pragma unroll
    for (int j = 0; j < 4; j++) {
        int cidx = lane + 32 * j;
        float hv = hr[cidx];
        const float* w = ow + cidx * 4;
        a0 = fmaf(hv, w[0], a0);
        a1 = fmaf(hv, w[1], a1);
        a2 = fmaf(hv, w[2], a2);
        a3 = fmaf(hv, w[3], a3);
    }
#pragma unroll
    for (int o = 16; o; o >>= 1) {
        a0 += __shfl_xor_sync(0xffffffffu, a0, o);
        a1 += __shfl_xor_sync(0xffffffffu, a1, o);
        a2 += __shfl_xor_sync(0xffffffffu, a2, o);
        a3 += __shfl_xor_sync(0xffffffffu, a3, o);
    }
    if (lane == 0) {
        *(float4*)(out + (size_t)row * 4) =
            make_float4(a0 + ob[0], a1 + ob[1], a2 + ob[2], a3 + ob[3]);
    }
}

// ---------------- launch -----------------------------------------------------
extern "C" void kernel_launch(void* const* d_in, const int* in_sizes, int n_in,
                              void* d_out, int out_size) {
    const float* x      = (const float*)d_in[0];
    const float* in_w   = (const float*)d_in[1];
    const float* in_b   = (const float*)d_in[2];
    const float* ln_g   = (const float*)d_in[3];
    const float* ln_b   = (const float*)d_in[4];
    const float* qkv_w  = (const float*)d_in[5];
    const float* qkv_b  = (const float*)d_in[6];
    const float* full_w = (const float*)d_in[7];
    const float* full_b = (const float*)d_in[8];
    const float* out_w  = (const float*)d_in[9];
    const float* out_b  = (const float*)d_in[10];
    float* out = (float*)d_out;

    inproj_kernel<<<MROWS, CH>>>(x, in_w, in_b);

    for (int l = 0; l < 4; l++) {
        ln_kernel<<<MROWS / 8, 256>>>(ln_g + l * CH, ln_b + l * CH);
        gemm_kernel<0><<<dim3(NQKV / 64, MROWS / 64), 256>>>(
            qkv_w + (size_t)l * CH * NQKV, qkv_b + l * NQKV);
        attn_kernel<<<dim3(SEQ / QT, TBS), 128>>>();
        gemm_kernel<1><<<dim3(CH / 64, MROWS / 64), 256>>>(
            full_w + (size_t)l * CH * CH, full_b + l * CH);
    }

    outproj_kernel<<<MROWS / 8, 256>>>(out_w, out_b, out);
}